// round 17
// baseline (speedup 1.0000x reference)
#include <cuda_runtime.h>
#include <cuda_bf16.h>

// Shapes (fixed by the problem):
//   x:      [B=32, CAT=10, C=32, H=32, W=32]  -> n = b*10+cat in [0,320)
//   weight: [h=32, w=32, O=64, C=32, 3, 3]    -> per-location [O][K=288], K contiguous
//   bias:   [CAT=10, O=64, 32, 32]
//   out:    [B=32, CAT=10, O=64, 32, 32]
//
// Pipeline:
//   1) transpose_in : x[n][chw] -> x_t[chw][n]           (coalesced both sides)
//   2) main         : per location GEMM [320x288]x[288x64], f32x2-packed FFMA,
//                     bias added, writes out_t[loc][n][o] (sector-coalesced)
//   3) transpose_out: out_t[loc][no] -> out[no][loc]      (coalesced both sides)

using u64 = unsigned long long;

#define NB   320          // batch*cat
#define CH   32
#define HH   32
#define WW   32
#define OO   64
#define KTOT 288          // C*3*3
#define KP_TOT 144        // KTOT/2
#define NLOC 1024         // 32*32
#define WS_STRIDE 145     // padded kp-stride (u64 elems) for bank-conflict-free o-lanes

// ---- scratch (device globals; no allocation) ----
__device__ float g_xt[CH * HH * WW * NB];          // 41.9 MB : x_t[c][h][w][n]
__device__ float g_ot[NLOC * NB * OO];             // 83.9 MB : out_t[loc][n][o]

union F2U { float2 f; u64 u; };

#define FMA2(d, a, b) asm("fma.rn.f32x2 %0, %1, %2, %0;" : "+l"(d) : "l"(a), "l"(b))

// ---------------------------------------------------------------------------
// transpose_in: x [320][32768] -> x_t [32768][320]
// ---------------------------------------------------------------------------
__global__ void __launch_bounds__(256) k_transpose_in(const float* __restrict__ x) {
    __shared__ float tile[32][33];
    int cbase = blockIdx.x * 32;           // chw tile base (0..32767)
    int nbase = blockIdx.y * 32;           // n tile base   (0..319)
    int tx = threadIdx.x, ty = threadIdx.y;
#pragma unroll
    for (int r = 0; r < 4; ++r) {
        int n = nbase + ty + r * 8;
        tile[ty + r * 8][tx] = x[(size_t)n * 32768 + cbase + tx];
    }
    __syncthreads();
#pragma unroll
    for (int r = 0; r < 4; ++r) {
        int chw = cbase + ty + r * 8;
        g_xt[(size_t)chw * NB + nbase + tx] = tile[tx][ty + r * 8];
    }
}

// ---------------------------------------------------------------------------
// main: one CTA per output location. 320 threads.
//   thread tid: og = tid&7 (owns o = og+8j, j=0..7), ng = tid>>3 (owns n = ng*8+i)
//   f32x2 lanes = (even k, odd k) partial sums; reduced in epilogue.
// ---------------------------------------------------------------------------
__global__ void __launch_bounds__(320, 1) k_local2d(
    const float* __restrict__ weight,
    const float* __restrict__ bias)
{
    extern __shared__ unsigned char smem_raw[];
    u64*   ws2  = (u64*)smem_raw;                       // [64][145] u64    = 74240 B
    u64*   xs2  = ws2 + OO * WS_STRIDE;                 // [8][320]  u64    = 20480 B
    float* bs   = (float*)(xs2 + 8 * NB);               // [10*64]   float  =  2560 B
    int*   ktab = (int*)(bs + 640);                     // [288]     int    =  1152 B

    const int tid = threadIdx.x;
    const int og  = tid & 7;
    const int ng8 = (tid >> 3) << 3;                    // ng*8
    const int loc = blockIdx.x;                         // h*32 + w
    const int h   = loc >> 5, w = loc & 31;

    // ---- stage weights: global [o][k] (k contiguous) -> ws2[o][kp] as f32x2 pairs
    {
        const u64* wg = (const u64*)(weight + (size_t)loc * (OO * KTOT)); // 8B elems = k-pairs
        for (int idx = tid; idx < OO * KP_TOT; idx += NB) {
            int o = idx / KP_TOT, kp = idx - o * KP_TOT;
            ws2[o * WS_STRIDE + kp] = wg[o * KP_TOT + kp];
        }
    }
    // ---- bias slice for this location: bs[cat*64+o]
    for (int t = tid; t < 640; t += NB) {
        int cat = t >> 6, o = t & 63;
        bs[t] = bias[((cat * OO + o) << 10) + loc];
    }
    // ---- k -> x_t offset table (premult by NB), -1 if padded-out-of-bounds
    for (int k = tid; k < KTOT; k += NB) {
        int c = k / 9, r2 = k - c * 9, p = r2 / 3, q = r2 - p * 3;
        int hp = h + p - 1, wp = w + q - 1;
        ktab[k] = (hp >= 0 && hp < HH && wp >= 0 && wp < WW)
                  ? ((c * HH + hp) * WW + wp) * NB : -1;
    }
    __syncthreads();

    u64 acc[64];
#pragma unroll
    for (int a = 0; a < 64; ++a) acc[a] = 0ull;

    const float* __restrict__ xt = g_xt;

    // prefetch stage 0 (16 k values, n = tid)
    float r[16];
#pragma unroll
    for (int kk = 0; kk < 16; ++kk) {
        int off = ktab[kk];
        r[kk] = (off >= 0) ? xt[off + tid] : 0.0f;
    }

    for (int s = 0; s < 18; ++s) {
        __syncthreads();     // previous stage fully consumed
#pragma unroll
        for (int kp = 0; kp < 8; ++kp) {
            F2U u; u.f = make_float2(r[2 * kp], r[2 * kp + 1]);
            xs2[kp * NB + tid] = u.u;
        }
        __syncthreads();     // stage visible
        if (s + 1 < 18) {
            const int kb = (s + 1) * 16;
#pragma unroll
            for (int kk = 0; kk < 16; ++kk) {
                int off = ktab[kb + kk];
                r[kk] = (off >= 0) ? xt[off + tid] : 0.0f;
            }
        }
        const u64* wbase = ws2 + og * WS_STRIDE + s * 8;
#pragma unroll
        for (int kp = 0; kp < 8; ++kp) {
            const ulonglong2* xr = (const ulonglong2*)(xs2 + kp * NB + ng8);
            ulonglong2 x0 = xr[0], x1 = xr[1], x2 = xr[2], x3 = xr[3];
            u64 xv0 = x0.x, xv1 = x0.y, xv2 = x1.x, xv3 = x1.y;
            u64 xv4 = x2.x, xv5 = x2.y, xv6 = x3.x, xv7 = x3.y;
#pragma unroll
            for (int j = 0; j < 8; ++j) {
                u64 wv = wbase[j * (8 * WS_STRIDE) + kp];
                FMA2(acc[0 * 8 + j], xv0, wv);
                FMA2(acc[1 * 8 + j], xv1, wv);
                FMA2(acc[2 * 8 + j], xv2, wv);
                FMA2(acc[3 * 8 + j], xv3, wv);
                FMA2(acc[4 * 8 + j], xv4, wv);
                FMA2(acc[5 * 8 + j], xv5, wv);
                FMA2(acc[6 * 8 + j], xv6, wv);
                FMA2(acc[7 * 8 + j], xv7, wv);
            }
        }
    }

    // ---- epilogue: reduce pair lanes, add bias, write out_t[loc][n][o]
    float* __restrict__ ot = g_ot + (size_t)loc * (NB * OO);
#pragma unroll
    for (int i = 0; i < 8; ++i) {
        int n = ng8 + i;
        int cat = n % 10;
        float* orow = ot + n * OO;
        const float* brow = bs + cat * OO;
#pragma unroll
        for (int j = 0; j < 8; ++j) {
            int o = og + 8 * j;
            F2U u; u.u = acc[i * 8 + j];
            orow[o] = u.f.x + u.f.y + brow[o];   // lanes(og) contiguous -> full 32B sectors
        }
    }
}

// ---------------------------------------------------------------------------
// transpose_out: out_t [1024][20480] -> out [20480][1024]
// ---------------------------------------------------------------------------
__global__ void __launch_bounds__(256) k_transpose_out(float* __restrict__ out) {
    __shared__ float tile[32][33];
    int nobase  = blockIdx.x * 32;         // (n*64+o) tile base
    int locbase = blockIdx.y * 32;         // loc tile base
    int tx = threadIdx.x, ty = threadIdx.y;
#pragma unroll
    for (int r = 0; r < 4; ++r) {
        int lc = locbase + ty + r * 8;
        tile[ty + r * 8][tx] = g_ot[(size_t)lc * (NB * OO) + nobase + tx];
    }
    __syncthreads();
#pragma unroll
    for (int r = 0; r < 4; ++r) {
        int no = nobase + ty + r * 8;
        out[(size_t)no * NLOC + locbase + tx] = tile[tx][ty + r * 8];
    }
}

// ---------------------------------------------------------------------------
extern "C" void kernel_launch(void* const* d_in, const int* in_sizes, int n_in,
                              void* d_out, int out_size) {
    const float* x      = (const float*)d_in[0];
    const float* weight = (const float*)d_in[1];
    const float* bias   = (const float*)d_in[2];
    float* out = (float*)d_out;

    static const int SMEM = OO * WS_STRIDE * 8 + 8 * NB * 8 + 640 * 4 + 288 * 4; // 98432
    cudaFuncSetAttribute(k_local2d, cudaFuncAttributeMaxDynamicSharedMemorySize, SMEM);

    dim3 bt(32, 8);
    k_transpose_in<<<dim3(1024, 10), bt>>>(x);
    k_local2d<<<NLOC, NB, SMEM>>>(weight, bias);
    k_transpose_out<<<dim3(640, 32), bt>>>(out);
}